// round 2
// baseline (speedup 1.0000x reference)
#include <cuda_runtime.h>
#include <math.h>

#define B_   2048
#define IN_  1024
#define E_   512
#define M_   256
#define NB_  8
#define H_   8
#define D_   64

// ---------------- scratch (static __device__, no allocations) ----------------
__device__ float g_encoded[B_*E_];
__device__ float g_mu[B_*NB_*E_];
__device__ float g_qp1[B_*NB_*E_];
__device__ float g_kp[M_*E_];
__device__ float g_vp[M_*E_];
__device__ float g_ctx1[B_*NB_*E_];
__device__ float g_att[B_*NB_*E_];
__device__ float g_ma[B_*E_];
__device__ float g_qp2[B_*E_];
__device__ float g_dv[B_*E_];
__device__ float g_ctx2[B_*E_];
__device__ float g_retr[B_*E_];

// ---------------- generic SGEMM: C[M,N] = act(A[M,K] @ B[N,K]^T + bias) -----
// NT layout (both A and B have K contiguous). 128x128 tile, BK=8, 256 thr,
// 8x8 per-thread microtile, double-buffered smem. All dims here are
// multiples of (128,128,8) by construction -> no bounds checks.
__global__ void __launch_bounds__(256) gemm_nt(
    const float* __restrict__ A, const float* __restrict__ Bm,
    const float* __restrict__ bias, float* __restrict__ C,
    int M, int N, int K, int act)
{
    __shared__ __align__(16) float As[2][8][128];
    __shared__ __align__(16) float Bs[2][8][128];
    const int tid = threadIdx.x;
    const int bm = blockIdx.y * 128;
    const int bn = blockIdx.x * 128;

    const int lr = tid >> 1;            // 0..127 row within tile
    const int lc = (tid & 1) << 2;      // 0 or 4 (k offset)
    const float* Ag = A  + (size_t)(bm + lr) * K + lc;
    const float* Bg = Bm + (size_t)(bn + lr) * K + lc;

    float acc[8][8];
    #pragma unroll
    for (int i = 0; i < 8; i++)
        #pragma unroll
        for (int j = 0; j < 8; j++) acc[i][j] = 0.f;

    // load tile 0
    {
        float4 a4 = *(const float4*)Ag;
        float4 b4 = *(const float4*)Bg;
        As[0][lc+0][lr] = a4.x; As[0][lc+1][lr] = a4.y;
        As[0][lc+2][lr] = a4.z; As[0][lc+3][lr] = a4.w;
        Bs[0][lc+0][lr] = b4.x; Bs[0][lc+1][lr] = b4.y;
        Bs[0][lc+2][lr] = b4.z; Bs[0][lc+3][lr] = b4.w;
    }
    __syncthreads();

    const int ty = tid >> 4;   // 0..15  (m)
    const int tx = tid & 15;   // 0..15  (n)
    int buf = 0;

    for (int kt = 0; kt < K; kt += 8) {
        float4 a4n, b4n;
        const bool more = (kt + 8) < K;
        if (more) {
            a4n = *(const float4*)(Ag + kt + 8);
            b4n = *(const float4*)(Bg + kt + 8);
        }
        #pragma unroll
        for (int kk = 0; kk < 8; kk++) {
            float4 a0 = *(const float4*)&As[buf][kk][ty*8];
            float4 a1 = *(const float4*)&As[buf][kk][ty*8+4];
            float4 b0 = *(const float4*)&Bs[buf][kk][tx*8];
            float4 b1 = *(const float4*)&Bs[buf][kk][tx*8+4];
            float ar[8] = {a0.x,a0.y,a0.z,a0.w,a1.x,a1.y,a1.z,a1.w};
            float br[8] = {b0.x,b0.y,b0.z,b0.w,b1.x,b1.y,b1.z,b1.w};
            #pragma unroll
            for (int i = 0; i < 8; i++)
                #pragma unroll
                for (int j = 0; j < 8; j++)
                    acc[i][j] = fmaf(ar[i], br[j], acc[i][j]);
        }
        if (more) {
            As[buf^1][lc+0][lr] = a4n.x; As[buf^1][lc+1][lr] = a4n.y;
            As[buf^1][lc+2][lr] = a4n.z; As[buf^1][lc+3][lr] = a4n.w;
            Bs[buf^1][lc+0][lr] = b4n.x; Bs[buf^1][lc+1][lr] = b4n.y;
            Bs[buf^1][lc+2][lr] = b4n.z; Bs[buf^1][lc+3][lr] = b4n.w;
        }
        __syncthreads();
        buf ^= 1;
    }

    float bv[8];
    #pragma unroll
    for (int j = 0; j < 8; j++) bv[j] = bias ? bias[bn + tx*8 + j] : 0.f;

    #pragma unroll
    for (int i = 0; i < 8; i++) {
        float* Cp = C + (size_t)(bm + ty*8 + i) * N + bn + tx*8;
        float v[8];
        #pragma unroll
        for (int j = 0; j < 8; j++) {
            float t = acc[i][j] + bv[j];
            v[j] = act ? tanhf(t) : t;
        }
        *(float4*)(Cp)     = make_float4(v[0], v[1], v[2], v[3]);
        *(float4*)(Cp + 4) = make_float4(v[4], v[5], v[6], v[7]);
    }
}

// ---------------- fused attention (Lk=256, D=64, shared K/V across batch) ---
// grid: (H, totalRows/64). Each block: one head, 64 q-rows. Warp handles 8 rows.
// Q rows laid out (row, e) with e = h*64+d. K/V are the 256x512 projected memory.
// dV (optional, only when lq==1): per-batch additive term to ctx.
#define ATTN_SMEM ((64*257 + 256*64 + 64*64 + 64*257) * 4)

__global__ void __launch_bounds__(256) attn_kernel(
    const float* __restrict__ Q, const float* __restrict__ Km,
    const float* __restrict__ Vm, const float* __restrict__ dV,
    float* __restrict__ O, int lq)
{
    extern __shared__ __align__(16) float sm[];
    float* KT = sm;                   // [64][257]  (d-major, padded)
    float* V  = KT + 64*257;          // [256][64]
    float* Qs = V  + 256*64;          // [64][64]
    float* Ss = Qs + 64*64;           // [64][257]  (probabilities, padded)

    const int h   = blockIdx.x;
    const int r0  = blockIdx.y * 64;
    const int tid = threadIdx.x;

    // cooperative loads
    for (int i = tid; i < 256*16; i += 256) {
        int k = i >> 4, dv = (i & 15) << 2;
        float4 kv = *(const float4*)(Km + (size_t)k*E_ + h*64 + dv);
        KT[(dv+0)*257 + k] = kv.x;
        KT[(dv+1)*257 + k] = kv.y;
        KT[(dv+2)*257 + k] = kv.z;
        KT[(dv+3)*257 + k] = kv.w;
        float4 vv = *(const float4*)(Vm + (size_t)k*E_ + h*64 + dv);
        *(float4*)(V + k*64 + dv) = vv;
    }
    for (int i = tid; i < 64*16; i += 256) {
        int r = i >> 4, dv = (i & 15) << 2;
        *(float4*)(Qs + r*64 + dv) =
            *(const float4*)(Q + (size_t)(r0 + r)*E_ + h*64 + dv);
    }
    __syncthreads();

    const int w    = tid >> 5;
    const int lane = tid & 31;
    const int wr   = w * 8;           // first of this warp's 8 rows

    // scores: s[r][j] for k = lane + 32*j
    float s[8][8];
    #pragma unroll
    for (int r = 0; r < 8; r++)
        #pragma unroll
        for (int j = 0; j < 8; j++) s[r][j] = 0.f;

    for (int d = 0; d < 64; d++) {
        float kk[8], q[8];
        #pragma unroll
        for (int j = 0; j < 8; j++) kk[j] = KT[d*257 + lane + 32*j];
        #pragma unroll
        for (int r = 0; r < 8; r++) q[r] = Qs[(wr + r)*64 + d];
        #pragma unroll
        for (int r = 0; r < 8; r++)
            #pragma unroll
            for (int j = 0; j < 8; j++)
                s[r][j] = fmaf(q[r], kk[j], s[r][j]);
    }

    // softmax over the 256 k's of each row
    #pragma unroll
    for (int r = 0; r < 8; r++) {
        float m = -1e30f;
        #pragma unroll
        for (int j = 0; j < 8; j++) { s[r][j] *= 0.125f; m = fmaxf(m, s[r][j]); }
        #pragma unroll
        for (int o = 16; o > 0; o >>= 1) m = fmaxf(m, __shfl_xor_sync(0xffffffffu, m, o));
        float sum = 0.f;
        #pragma unroll
        for (int j = 0; j < 8; j++) { s[r][j] = __expf(s[r][j] - m); sum += s[r][j]; }
        #pragma unroll
        for (int o = 16; o > 0; o >>= 1) sum += __shfl_xor_sync(0xffffffffu, sum, o);
        float inv = 1.f / sum;
        #pragma unroll
        for (int j = 0; j < 8; j++) Ss[(wr + r)*257 + lane + 32*j] = s[r][j] * inv;
    }
    __syncwarp();

    // ctx: lane owns d = lane and d = lane+32
    float a0[8], a1[8];
    #pragma unroll
    for (int r = 0; r < 8; r++) { a0[r] = 0.f; a1[r] = 0.f; }
    for (int k = 0; k < 256; k++) {
        float v0 = V[k*64 + lane];
        float v1 = V[k*64 + lane + 32];
        #pragma unroll
        for (int r = 0; r < 8; r++) {
            float p = Ss[(wr + r)*257 + k];
            a0[r] = fmaf(p, v0, a0[r]);
            a1[r] = fmaf(p, v1, a1[r]);
        }
    }

    #pragma unroll
    for (int r = 0; r < 8; r++) {
        int row = r0 + wr + r;
        float add0 = 0.f, add1 = 0.f;
        if (dV) {
            int b = row / lq;
            add0 = dV[(size_t)b*E_ + h*64 + lane];
            add1 = dV[(size_t)b*E_ + h*64 + lane + 32];
        }
        O[(size_t)row*E_ + h*64 + lane]      = a0[r] + add0;
        O[(size_t)row*E_ + h*64 + lane + 32] = a1[r] + add1;
    }
}

// ---------------- small elementwise kernels ----------------------------------
__global__ void mean_over_q(const float* __restrict__ att, float* __restrict__ ma)
{
    int i = blockIdx.x * blockDim.x + threadIdx.x;   // over B_*E_
    int b = i >> 9, e = i & 511;
    const float* p = att + ((size_t)b * NB_) * E_ + e;
    float s = 0.f;
    #pragma unroll
    for (int q = 0; q < NB_; q++) s += p[(size_t)q * E_];
    ma[i] = s * (1.f / NB_);
}

// out[b,k,e] = memory[k,e] + ma[b,e]   (the 1.07 GB output tensor)
__global__ void write_um(const float* __restrict__ mem, const float* __restrict__ ma,
                         float* __restrict__ out)
{
    size_t i = (size_t)blockIdx.x * blockDim.x + threadIdx.x;  // float4 index
    size_t e4 = i & 127;                 // E_/4 = 128
    size_t k  = (i >> 7) & 255;
    size_t b  = i >> 15;
    float4 m4 = ((const float4*)mem)[k * 128 + e4];
    float4 a4 = ((const float4*)ma)[b * 128 + e4];
    ((float4*)out)[i] = make_float4(m4.x + a4.x, m4.y + a4.y, m4.z + a4.z, m4.w + a4.w);
}

// ---------------- launch ------------------------------------------------------
extern "C" void kernel_launch(void* const* d_in, const int* in_sizes, int n_in,
                              void* d_out, int out_size)
{
    const float* x     = (const float*)d_in[0];
    const float* mem   = (const float*)d_in[1];
    const float* enc_w = (const float*)d_in[2];
    const float* enc_b = (const float*)d_in[3];
    const float* blk_w = (const float*)d_in[4];
    const float* blk_b = (const float*)d_in[5];
    const float* in_w  = (const float*)d_in[6];
    const float* in_b  = (const float*)d_in[7];
    const float* out_w = (const float*)d_in[8];
    const float* out_b = (const float*)d_in[9];
    const float* dec_w = (const float*)d_in[10];
    const float* dec_b = (const float*)d_in[11];

    float* out    = (float*)d_out;                   // (B, IN)
    float* out_um = out + (size_t)B_ * IN_;          // (B, M, E)

    float *encoded, *mu, *qp1, *kp, *vp, *ctx1, *att, *ma, *qp2, *dv, *ctx2, *retr;
    cudaGetSymbolAddress((void**)&encoded, g_encoded);
    cudaGetSymbolAddress((void**)&mu,      g_mu);
    cudaGetSymbolAddress((void**)&qp1,     g_qp1);
    cudaGetSymbolAddress((void**)&kp,      g_kp);
    cudaGetSymbolAddress((void**)&vp,      g_vp);
    cudaGetSymbolAddress((void**)&ctx1,    g_ctx1);
    cudaGetSymbolAddress((void**)&att,     g_att);
    cudaGetSymbolAddress((void**)&ma,      g_ma);
    cudaGetSymbolAddress((void**)&qp2,     g_qp2);
    cudaGetSymbolAddress((void**)&dv,      g_dv);
    cudaGetSymbolAddress((void**)&ctx2,    g_ctx2);
    cudaGetSymbolAddress((void**)&retr,    g_retr);

    const float* wq = in_w;
    const float* bq = in_b;
    const float* wk = in_w + 512*512;
    const float* bk = in_b + 512;
    const float* wv = in_w + 1024*512;
    const float* bv = in_b + 1024;

    cudaFuncSetAttribute(attn_kernel, cudaFuncAttributeMaxDynamicSharedMemorySize, ATTN_SMEM);

    dim3 thr(256);

    // encoded = tanh(x @ enc_w^T + enc_b)                       [2048 x 512]
    gemm_nt<<<dim3(E_/128, B_/128), thr>>>(x, enc_w, enc_b, encoded, B_, E_, IN_, 1);
    // memory_updates = encoded @ blk_w_flat^T + blk_b_flat      [2048 x 4096]
    gemm_nt<<<dim3(4096/128, B_/128), thr>>>(encoded, blk_w, blk_b, mu, B_, NB_*E_, E_, 0);
    // qp1 = mu @ wq^T + bq                                      [16384 x 512]
    gemm_nt<<<dim3(E_/128, (B_*NB_)/128), thr>>>(mu, wq, bq, qp1, B_*NB_, E_, E_, 0);
    // kp_mem / vp_mem (shared across batch — broadcast K/V)     [256 x 512]
    gemm_nt<<<dim3(E_/128, M_/128), thr>>>(mem, wk, bk, kp, M_, E_, E_, 0);
    gemm_nt<<<dim3(E_/128, M_/128), thr>>>(mem, wv, bv, vp, M_, E_, E_, 0);
    // MHA1 attention core
    attn_kernel<<<dim3(H_, (B_*NB_)/64), thr, ATTN_SMEM>>>(qp1, kp, vp, nullptr, ctx1, NB_);
    // attended = ctx1 @ out_w^T + out_b                         [16384 x 512]
    gemm_nt<<<dim3(E_/128, (B_*NB_)/128), thr>>>(ctx1, out_w, out_b, att, B_*NB_, E_, E_, 0);
    // ma = mean over Lq
    mean_over_q<<<(B_*E_)/256, thr>>>(att, ma);
    // updated_memory output (rank-1 expanded)
    write_um<<<((size_t)B_*M_*E_/4)/256, thr>>>(mem, ma, out_um);
    // qp2 = encoded @ wq^T + bq                                 [2048 x 512]
    gemm_nt<<<dim3(E_/128, B_/128), thr>>>(encoded, wq, bq, qp2, B_, E_, E_, 0);
    // dv = ma @ wv^T (no bias; bias already inside vp_mem)      [2048 x 512]
    gemm_nt<<<dim3(E_/128, B_/128), thr>>>(ma, wv, nullptr, dv, B_, E_, E_, 0);
    // MHA2 attention core (scores use kp_mem only: batch term is softmax-invariant)
    attn_kernel<<<dim3(H_, B_/64), thr, ATTN_SMEM>>>(qp2, kp, vp, dv, ctx2, 1);
    // retrieved = ctx2 @ out_w^T + out_b                        [2048 x 512]
    gemm_nt<<<dim3(E_/128, B_/128), thr>>>(ctx2, out_w, out_b, retr, B_, E_, E_, 0);
    // output = retrieved @ dec_w^T + dec_b                      [2048 x 1024]
    gemm_nt<<<dim3(IN_/128, B_/128), thr>>>(retr, dec_w, dec_b, out, B_, IN_, E_, 0);
}

// round 8
// speedup vs baseline: 1.4928x; 1.4928x over previous
#include <cuda_runtime.h>
#include <cuda_bf16.h>
#include <cstdint>
#include <math.h>

#define B_   2048
#define IN_  1024
#define E_   512
#define M_   256
#define NB_  8
#define H_   8
#define D_   64

// ---------------- scratch (static __device__, no allocations) ----------------
__device__ float g_encoded[B_*E_];
__device__ float g_mu[B_*NB_*E_];
__device__ float g_qp1[B_*NB_*E_];
__device__ float g_kp[M_*E_];
__device__ float g_vp[M_*E_];
__device__ float g_ctx1[B_*NB_*E_];
__device__ float g_att[B_*NB_*E_];
__device__ float g_ma[B_*E_];
__device__ float g_qp2[B_*E_];
__device__ float g_dv[B_*E_];
__device__ float g_ctx2[B_*E_];
__device__ float g_retr[B_*E_];

// ---------------- helpers ----------------------------------------------------
__device__ __forceinline__ uint32_t smem_to_u32(const void* p) {
    uint32_t a;
    asm("{ .reg .u64 t; cvta.to.shared.u64 t, %1; cvt.u32.u64 %0, t; }"
        : "=r"(a) : "l"(p));
    return a;
}
__device__ __forceinline__ void ldm_x4(uint32_t& r0, uint32_t& r1, uint32_t& r2,
                                       uint32_t& r3, uint32_t addr) {
    asm volatile("ldmatrix.sync.aligned.m8n8.x4.shared.b16 {%0,%1,%2,%3}, [%4];"
        : "=r"(r0), "=r"(r1), "=r"(r2), "=r"(r3) : "r"(addr));
}
__device__ __forceinline__ void mma_bf16(float* c, const uint32_t* a,
                                         uint32_t b0, uint32_t b1) {
    asm volatile(
        "mma.sync.aligned.m16n8k16.row.col.f32.bf16.bf16.f32 "
        "{%0,%1,%2,%3}, {%4,%5,%6,%7}, {%8,%9}, {%0,%1,%2,%3};"
        : "+f"(c[0]), "+f"(c[1]), "+f"(c[2]), "+f"(c[3])
        : "r"(a[0]), "r"(a[1]), "r"(a[2]), "r"(a[3]), "r"(b0), "r"(b1));
}
// fp32 -> (hi bf16x2, lo bf16x2)
__device__ __forceinline__ void cvt2(float a, float b, uint32_t& h, uint32_t& l) {
    __nv_bfloat162 H;
    H.x = __float2bfloat16_rn(a);
    H.y = __float2bfloat16_rn(b);
    float ra = a - __bfloat162float(H.x);
    float rb = b - __bfloat162float(H.y);
    __nv_bfloat162 L = __floats2bfloat162_rn(ra, rb);
    h = *reinterpret_cast<uint32_t*>(&H);
    l = *reinterpret_cast<uint32_t*>(&L);
}

// ============ tensor-core SGEMM: C[M,N] = act(A[M,K] @ B[N,K]^T + bias) ======
// bf16x3 emulation via mma.sync (HMMA, base-ISA — no 'a'-only features).
// 128x128 CTA tile, BK=32, 256 thr, 8 warps (2x4), warp tile 64x32.
// smem rows: 32 bf16 + 8 pad = 80B stride -> conflict-free ldmatrix.
#define GT_THREADS 256
#define RSTRIDE 80
#define TB (128*RSTRIDE)          // 10240 bytes per tile piece
#define GT_SMEM (8*TB + 512)      // 2 bufs x {Ah,Al,Bh,Bl} + bias

__global__ void __launch_bounds__(GT_THREADS)
gemm_tc(const float* __restrict__ A, const float* __restrict__ Bm,
        const float* __restrict__ bias, float* __restrict__ C,
        int M, int N, int K, int act)
{
    extern __shared__ __align__(16) char sm[];
    float* bias_s = (float*)(sm + 8*TB);
    const uint32_t smb = smem_to_u32(sm);

    const int tid  = threadIdx.x;
    const int wid  = tid >> 5;
    const int lane = tid & 31;
    const int wm   = wid >> 2;        // 0..1
    const int wn   = wid & 3;         // 0..3
    const int bm = blockIdx.y * 128;
    const int bn = blockIdx.x * 128;

    if (tid < 128) bias_s[tid] = bias ? bias[bn + tid] : 0.f;

    // loader mapping: 4 chunks each; chunk = tid + 256*i; row = chunk>>3, c4 = chunk&7
    float4 pa[4], pb[4];
    #define LOAD_G(kt) do { \
        _Pragma("unroll") \
        for (int i = 0; i < 4; i++) { \
            int ch = tid + 256*i; int row = ch >> 3, c4 = ch & 7; \
            pa[i] = *(const float4*)(A  + (size_t)(bm + row)*K + (kt) + c4*4); \
            pb[i] = *(const float4*)(Bm + (size_t)(bn + row)*K + (kt) + c4*4); \
        } } while(0)
    #define STORE_S(b) do { \
        char* base = sm + (b)*4*TB; \
        _Pragma("unroll") \
        for (int i = 0; i < 4; i++) { \
            int ch = tid + 256*i; int row = ch >> 3, c4 = ch & 7; \
            int off = row*RSTRIDE + c4*8; \
            uint32_t h0, l0, h1, l1; \
            cvt2(pa[i].x, pa[i].y, h0, l0); cvt2(pa[i].z, pa[i].w, h1, l1); \
            *(uint2*)(base + off)      = make_uint2(h0, h1); \
            *(uint2*)(base + TB + off) = make_uint2(l0, l1); \
            cvt2(pb[i].x, pb[i].y, h0, l0); cvt2(pb[i].z, pb[i].w, h1, l1); \
            *(uint2*)(base + 2*TB + off) = make_uint2(h0, h1); \
            *(uint2*)(base + 3*TB + off) = make_uint2(l0, l1); \
        } } while(0)

    float c[4][4][4];
    #pragma unroll
    for (int i = 0; i < 4; i++)
        #pragma unroll
        for (int j = 0; j < 4; j++)
            #pragma unroll
            for (int q = 0; q < 4; q++) c[i][j][q] = 0.f;

    LOAD_G(0);
    STORE_S(0);
    __syncthreads();

    const int Kt = K >> 5;
    const int rowsel = lane & 15;
    const uint32_t kbhalf = (uint32_t)(lane >> 4) * 16;

    for (int it = 0; it < Kt; it++) {
        const int b = it & 1;
        const bool more = (it + 1) < Kt;
        if (more) LOAD_G((it + 1) * 32);

        const uint32_t aH = smb + (uint32_t)b*4*TB;
        const uint32_t aL = aH + TB;
        const uint32_t bH = aH + 2*TB;
        const uint32_t bL = aH + 3*TB;

        #pragma unroll
        for (int ks = 0; ks < 2; ks++) {
            const uint32_t kb = kbhalf + ks*32;
            uint32_t ah[4][4], al[4][4], bh[2][4], bl[2][4];
            #pragma unroll
            for (int mf = 0; mf < 4; mf++) {
                uint32_t ra = (uint32_t)(wm*64 + mf*16 + rowsel)*RSTRIDE + kb;
                ldm_x4(ah[mf][0], ah[mf][1], ah[mf][2], ah[mf][3], aH + ra);
                ldm_x4(al[mf][0], al[mf][1], al[mf][2], al[mf][3], aL + ra);
            }
            #pragma unroll
            for (int ng = 0; ng < 2; ng++) {
                uint32_t rb = (uint32_t)(wn*32 + ng*16 + rowsel)*RSTRIDE + kb;
                ldm_x4(bh[ng][0], bh[ng][1], bh[ng][2], bh[ng][3], bH + rb);
                ldm_x4(bl[ng][0], bl[ng][1], bl[ng][2], bl[ng][3], bL + rb);
            }
            #pragma unroll
            for (int mf = 0; mf < 4; mf++)
                #pragma unroll
                for (int nf = 0; nf < 4; nf++) {
                    const int ng = nf >> 1, s = nf & 1;
                    mma_bf16(c[mf][nf], ah[mf], bh[ng][s], bh[ng][s+2]);
                    mma_bf16(c[mf][nf], ah[mf], bl[ng][s], bl[ng][s+2]);
                    mma_bf16(c[mf][nf], al[mf], bh[ng][s], bh[ng][s+2]);
                }
        }
        if (more) { __syncthreads(); STORE_S(b ^ 1); }
        __syncthreads();
    }

    // epilogue: thread owns rows (lane>>2, +8), col pairs 2*(lane&3)
    #pragma unroll
    for (int mf = 0; mf < 4; mf++) {
        #pragma unroll
        for (int nf = 0; nf < 4; nf++) {
            int r0 = bm + wm*64 + mf*16 + (lane >> 2);
            int cl = wn*32 + nf*8 + (lane & 3)*2;
            float2 v0, v1;
            v0.x = c[mf][nf][0] + bias_s[cl];
            v0.y = c[mf][nf][1] + bias_s[cl+1];
            v1.x = c[mf][nf][2] + bias_s[cl];
            v1.y = c[mf][nf][3] + bias_s[cl+1];
            if (act) {
                v0.x = tanhf(v0.x); v0.y = tanhf(v0.y);
                v1.x = tanhf(v1.x); v1.y = tanhf(v1.y);
            }
            *(float2*)(C + (size_t)r0 * N + bn + cl)       = v0;
            *(float2*)(C + (size_t)(r0 + 8) * N + bn + cl) = v1;
        }
    }
}

// ---------------- fused attention (Lk=256, D=64, shared K/V across batch) ---
#define ATTN_SMEM ((64*257 + 256*64 + 64*64 + 64*257) * 4)

__global__ void __launch_bounds__(256) attn_kernel(
    const float* __restrict__ Q, const float* __restrict__ Km,
    const float* __restrict__ Vm, const float* __restrict__ dV,
    float* __restrict__ O, int lq)
{
    extern __shared__ __align__(16) float smf[];
    float* KT = smf;                  // [64][257]
    float* V  = KT + 64*257;          // [256][64]
    float* Qs = V  + 256*64;          // [64][64]
    float* Ss = Qs + 64*64;           // [64][257]

    const int h   = blockIdx.x;
    const int r0  = blockIdx.y * 64;
    const int tid = threadIdx.x;

    for (int i = tid; i < 256*16; i += 256) {
        int k = i >> 4, dv = (i & 15) << 2;
        float4 kv = *(const float4*)(Km + (size_t)k*E_ + h*64 + dv);
        KT[(dv+0)*257 + k] = kv.x;
        KT[(dv+1)*257 + k] = kv.y;
        KT[(dv+2)*257 + k] = kv.z;
        KT[(dv+3)*257 + k] = kv.w;
        float4 vv = *(const float4*)(Vm + (size_t)k*E_ + h*64 + dv);
        *(float4*)(V + k*64 + dv) = vv;
    }
    for (int i = tid; i < 64*16; i += 256) {
        int r = i >> 4, dv = (i & 15) << 2;
        *(float4*)(Qs + r*64 + dv) =
            *(const float4*)(Q + (size_t)(r0 + r)*E_ + h*64 + dv);
    }
    __syncthreads();

    const int w    = tid >> 5;
    const int lane = tid & 31;
    const int wr   = w * 8;

    float s[8][8];
    #pragma unroll
    for (int r = 0; r < 8; r++)
        #pragma unroll
        for (int j = 0; j < 8; j++) s[r][j] = 0.f;

    for (int d = 0; d < 64; d++) {
        float kk[8], q[8];
        #pragma unroll
        for (int j = 0; j < 8; j++) kk[j] = KT[d*257 + lane + 32*j];
        #pragma unroll
        for (int r = 0; r < 8; r++) q[r] = Qs[(wr + r)*64 + d];
        #pragma unroll
        for (int r = 0; r < 8; r++)
            #pragma unroll
            for (int j = 0; j < 8; j++)
                s[r][j] = fmaf(q[r], kk[j], s[r][j]);
    }

    #pragma unroll
    for (int r = 0; r < 8; r++) {
        float m = -1e30f;
        #pragma unroll
        for (int j = 0; j < 8; j++) { s[r][j] *= 0.125f; m = fmaxf(m, s[r][j]); }
        #pragma unroll
        for (int o = 16; o > 0; o >>= 1) m = fmaxf(m, __shfl_xor_sync(0xffffffffu, m, o));
        float sum = 0.f;
        #pragma unroll
        for (int j = 0; j < 8; j++) { s[r][j] = __expf(s[r][j] - m); sum += s[r][j]; }
        #pragma unroll
        for (int o = 16; o > 0; o >>= 1) sum += __shfl_xor_sync(0xffffffffu, sum, o);
        float inv = 1.f / sum;
        #pragma unroll
        for (int j = 0; j < 8; j++) Ss[(wr + r)*257 + lane + 32*j] = s[r][j] * inv;
    }
    __syncwarp();

    float a0[8], a1[8];
    #pragma unroll
    for (int r = 0; r < 8; r++) { a0[r] = 0.f; a1[r] = 0.f; }
    for (int k = 0; k < 256; k++) {
        float v0 = V[k*64 + lane];
        float v1 = V[k*64 + lane + 32];
        #pragma unroll
        for (int r = 0; r < 8; r++) {
            float p = Ss[(wr + r)*257 + k];
            a0[r] = fmaf(p, v0, a0[r]);
            a1[r] = fmaf(p, v1, a1[r]);
        }
    }

    #pragma unroll
    for (int r = 0; r < 8; r++) {
        int row = r0 + wr + r;
        float add0 = 0.f, add1 = 0.f;
        if (dV) {
            int b = row / lq;
            add0 = dV[(size_t)b*E_ + h*64 + lane];
            add1 = dV[(size_t)b*E_ + h*64 + lane + 32];
        }
        O[(size_t)row*E_ + h*64 + lane]      = a0[r] + add0;
        O[(size_t)row*E_ + h*64 + lane + 32] = a1[r] + add1;
    }
}

// ---------------- small elementwise kernels ----------------------------------
__global__ void mean_over_q(const float* __restrict__ att, float* __restrict__ ma)
{
    int i = blockIdx.x * blockDim.x + threadIdx.x;
    int b = i >> 9;
    const float* p = att + ((size_t)b * NB_) * E_ + (i & 511);
    float s = 0.f;
    #pragma unroll
    for (int q = 0; q < NB_; q++) s += p[(size_t)q * E_];
    ma[i] = s * (1.f / NB_);
}

__global__ void write_um(const float* __restrict__ mem, const float* __restrict__ ma,
                         float* __restrict__ out)
{
    size_t i = (size_t)blockIdx.x * blockDim.x + threadIdx.x;
    size_t e4 = i & 127;
    size_t k  = (i >> 7) & 255;
    size_t b  = i >> 15;
    float4 m4 = ((const float4*)mem)[k * 128 + e4];
    float4 a4 = ((const float4*)ma)[b * 128 + e4];
    ((float4*)out)[i] = make_float4(m4.x + a4.x, m4.y + a4.y, m4.z + a4.z, m4.w + a4.w);
}

// ---------------- launch ------------------------------------------------------
extern "C" void kernel_launch(void* const* d_in, const int* in_sizes, int n_in,
                              void* d_out, int out_size)
{
    const float* x     = (const float*)d_in[0];
    const float* mem   = (const float*)d_in[1];
    const float* enc_w = (const float*)d_in[2];
    const float* enc_b = (const float*)d_in[3];
    const float* blk_w = (const float*)d_in[4];
    const float* blk_b = (const float*)d_in[5];
    const float* in_w  = (const float*)d_in[6];
    const float* in_b  = (const float*)d_in[7];
    const float* out_w = (const float*)d_in[8];
    const float* out_b = (const float*)d_in[9];
    const float* dec_w = (const float*)d_in[10];
    const float* dec_b = (const float*)d_in[11];

    float* out    = (float*)d_out;                   // (B, IN)
    float* out_um = out + (size_t)B_ * IN_;          // (B, M, E)

    float *encoded, *mu, *qp1, *kp, *vp, *ctx1, *att, *ma, *qp2, *dv, *ctx2, *retr;
    cudaGetSymbolAddress((void**)&encoded, g_encoded);
    cudaGetSymbolAddress((void**)&mu,      g_mu);
    cudaGetSymbolAddress((void**)&qp1,     g_qp1);
    cudaGetSymbolAddress((void**)&kp,      g_kp);
    cudaGetSymbolAddress((void**)&vp,      g_vp);
    cudaGetSymbolAddress((void**)&ctx1,    g_ctx1);
    cudaGetSymbolAddress((void**)&att,     g_att);
    cudaGetSymbolAddress((void**)&ma,      g_ma);
    cudaGetSymbolAddress((void**)&qp2,     g_qp2);
    cudaGetSymbolAddress((void**)&dv,      g_dv);
    cudaGetSymbolAddress((void**)&ctx2,    g_ctx2);
    cudaGetSymbolAddress((void**)&retr,    g_retr);

    const float* wq = in_w;
    const float* bq = in_b;
    const float* wk = in_w + 512*512;
    const float* bk = in_b + 512;
    const float* wv = in_w + 1024*512;
    const float* bv = in_b + 1024;

    cudaFuncSetAttribute(gemm_tc, cudaFuncAttributeMaxDynamicSharedMemorySize, GT_SMEM);
    cudaFuncSetAttribute(attn_kernel, cudaFuncAttributeMaxDynamicSharedMemorySize, ATTN_SMEM);

    dim3 thr(GT_THREADS);
    dim3 thr2(256);

    // encoded = tanh(x @ enc_w^T + enc_b)                       [2048 x 512] K=1024
    gemm_tc<<<dim3(E_/128, B_/128), thr, GT_SMEM>>>(x, enc_w, enc_b, encoded, B_, E_, IN_, 1);
    // memory_updates = encoded @ blk_w_flat^T + blk_b_flat      [2048 x 4096]
    gemm_tc<<<dim3(4096/128, B_/128), thr, GT_SMEM>>>(encoded, blk_w, blk_b, mu, B_, NB_*E_, E_, 0);
    // qp1 = mu @ wq^T + bq                                      [16384 x 512]
    gemm_tc<<<dim3(E_/128, (B_*NB_)/128), thr, GT_SMEM>>>(mu, wq, bq, qp1, B_*NB_, E_, E_, 0);
    // kp_mem / vp_mem (shared across batch)                     [256 x 512]
    gemm_tc<<<dim3(E_/128, M_/128), thr, GT_SMEM>>>(mem, wk, bk, kp, M_, E_, E_, 0);
    gemm_tc<<<dim3(E_/128, M_/128), thr, GT_SMEM>>>(mem, wv, bv, vp, M_, E_, E_, 0);
    // MHA1 attention core
    attn_kernel<<<dim3(H_, (B_*NB_)/64), thr2, ATTN_SMEM>>>(qp1, kp, vp, nullptr, ctx1, NB_);
    // attended = ctx1 @ out_w^T + out_b                         [16384 x 512]
    gemm_tc<<<dim3(E_/128, (B_*NB_)/128), thr, GT_SMEM>>>(ctx1, out_w, out_b, att, B_*NB_, E_, E_, 0);
    // ma = mean over Lq
    mean_over_q<<<(B_*E_)/256, thr2>>>(att, ma);
    // updated_memory output (rank-1 expanded)
    write_um<<<((size_t)B_*M_*E_/4)/256, thr2>>>(mem, ma, out_um);
    // qp2 = encoded @ wq^T + bq                                 [2048 x 512]
    gemm_tc<<<dim3(E_/128, B_/128), thr, GT_SMEM>>>(encoded, wq, bq, qp2, B_, E_, E_, 0);
    // dv = ma @ wv^T (no bias; bias already inside vp_mem)      [2048 x 512]
    gemm_tc<<<dim3(E_/128, B_/128), thr, GT_SMEM>>>(ma, wv, nullptr, dv, B_, E_, E_, 0);
    // MHA2 attention core (batch score term is softmax-invariant)
    attn_kernel<<<dim3(H_, B_/64), thr2, ATTN_SMEM>>>(qp2, kp, vp, dv, ctx2, 1);
    // retrieved = ctx2 @ out_w^T + out_b                        [2048 x 512]
    gemm_tc<<<dim3(E_/128, B_/128), thr, GT_SMEM>>>(ctx2, out_w, out_b, retr, B_, E_, E_, 0);
    // output = retrieved @ dec_w^T + dec_b                      [2048 x 1024]
    gemm_tc<<<dim3(IN_/128, B_/128), thr, GT_SMEM>>>(retr, dec_w, dec_b, out, B_, IN_, E_, 0);
}

// round 13
// speedup vs baseline: 1.6440x; 1.1013x over previous
#include <cuda_runtime.h>
#include <cuda_bf16.h>
#include <cstdint>
#include <math.h>

#define B_   2048
#define IN_  1024
#define E_   512
#define M_   256
#define NB_  8
#define H_   8
#define D_   64

// ---------------- scratch (static __device__, no allocations) ----------------
__device__ float g_encoded[B_*E_];
__device__ float g_mu[B_*NB_*E_];
__device__ float g_qp1[B_*NB_*E_];
__device__ float g_kpv[M_*2*E_];      // kp | vp side by side, row stride 1024
__device__ float g_ctx1[B_*NB_*E_];
__device__ float g_ma[B_*E_];
__device__ float g_qp2[B_*E_];
__device__ float g_dv[B_*E_];
__device__ float g_ctx2[B_*E_];
__device__ float g_retr[B_*E_];

// ---------------- helpers ----------------------------------------------------
__device__ __forceinline__ uint32_t smem_to_u32(const void* p) {
    uint32_t a;
    asm("{ .reg .u64 t; cvta.to.shared.u64 t, %1; cvt.u32.u64 %0, t; }"
        : "=r"(a) : "l"(p));
    return a;
}
__device__ __forceinline__ void ldm_x4(uint32_t& r0, uint32_t& r1, uint32_t& r2,
                                       uint32_t& r3, uint32_t addr) {
    asm volatile("ldmatrix.sync.aligned.m8n8.x4.shared.b16 {%0,%1,%2,%3}, [%4];"
        : "=r"(r0), "=r"(r1), "=r"(r2), "=r"(r3) : "r"(addr));
}
__device__ __forceinline__ void mma_bf16(float* c, const uint32_t* a,
                                         uint32_t b0, uint32_t b1) {
    asm volatile(
        "mma.sync.aligned.m16n8k16.row.col.f32.bf16.bf16.f32 "
        "{%0,%1,%2,%3}, {%4,%5,%6,%7}, {%8,%9}, {%0,%1,%2,%3};"
        : "+f"(c[0]), "+f"(c[1]), "+f"(c[2]), "+f"(c[3])
        : "r"(a[0]), "r"(a[1]), "r"(a[2]), "r"(a[3]), "r"(b0), "r"(b1));
}
// fp32 -> (hi bf16x2, lo bf16x2)
__device__ __forceinline__ void cvt2(float a, float b, uint32_t& h, uint32_t& l) {
    __nv_bfloat162 H;
    H.x = __float2bfloat16_rn(a);
    H.y = __float2bfloat16_rn(b);
    float ra = a - __bfloat162float(H.x);
    float rb = b - __bfloat162float(H.y);
    __nv_bfloat162 L = __floats2bfloat162_rn(ra, rb);
    h = *reinterpret_cast<uint32_t*>(&H);
    l = *reinterpret_cast<uint32_t*>(&L);
}
// packed f32x2 (sm_100+ base ISA)
__device__ __forceinline__ unsigned long long pk2(float x, float y) {
    unsigned long long r;
    asm("mov.b64 %0, {%1, %2};" : "=l"(r) : "f"(x), "f"(y));
    return r;
}
__device__ __forceinline__ void upk2(unsigned long long v, float& x, float& y) {
    asm("mov.b64 {%0, %1}, %2;" : "=f"(x), "=f"(y) : "l"(v));
}
__device__ __forceinline__ void fma2(unsigned long long& d, unsigned long long a,
                                     unsigned long long b) {
    asm("fma.rn.f32x2 %0, %1, %2, %0;" : "+l"(d) : "l"(a), "l"(b));
}

// ============ tensor-core SGEMM: C[M,N] = act(A[M,K] @ B[N,K]^T + bias) ======
// bf16x3 emulation via mma.sync. 128x128 CTA tile, BK=32, 256 thr.
// act: 0=none, 1=tanh, 2=mean-reduce rows by 8 into C[bm/8+b][*] (no full write)
#define GT_THREADS 256
#define RSTRIDE 80
#define TB (128*RSTRIDE)          // 10240 bytes per tile piece
#define GT_SMEM (8*TB + 512)      // 2 bufs x {Ah,Al,Bh,Bl} + bias

__global__ void __launch_bounds__(GT_THREADS)
gemm_tc(const float* __restrict__ A, const float* __restrict__ Bm,
        const float* __restrict__ bias, float* __restrict__ C,
        int M, int N, int K, int act)
{
    extern __shared__ __align__(16) char sm[];
    float* bias_s = (float*)(sm + 8*TB);
    const uint32_t smb = smem_to_u32(sm);

    const int tid  = threadIdx.x;
    const int wid  = tid >> 5;
    const int lane = tid & 31;
    const int wm   = wid >> 2;        // 0..1
    const int wn   = wid & 3;         // 0..3
    const int bm = blockIdx.y * 128;
    const int bn = blockIdx.x * 128;

    if (tid < 128) bias_s[tid] = bias ? bias[bn + tid] : 0.f;

    float4 pa[4], pb[4];
    #define LOAD_G(kt) do { \
        _Pragma("unroll") \
        for (int i = 0; i < 4; i++) { \
            int ch = tid + 256*i; int row = ch >> 3, c4 = ch & 7; \
            pa[i] = *(const float4*)(A  + (size_t)(bm + row)*K + (kt) + c4*4); \
            pb[i] = *(const float4*)(Bm + (size_t)(bn + row)*K + (kt) + c4*4); \
        } } while(0)
    #define STORE_S(b) do { \
        char* base = sm + (b)*4*TB; \
        _Pragma("unroll") \
        for (int i = 0; i < 4; i++) { \
            int ch = tid + 256*i; int row = ch >> 3, c4 = ch & 7; \
            int off = row*RSTRIDE + c4*8; \
            uint32_t h0, l0, h1, l1; \
            cvt2(pa[i].x, pa[i].y, h0, l0); cvt2(pa[i].z, pa[i].w, h1, l1); \
            *(uint2*)(base + off)      = make_uint2(h0, h1); \
            *(uint2*)(base + TB + off) = make_uint2(l0, l1); \
            cvt2(pb[i].x, pb[i].y, h0, l0); cvt2(pb[i].z, pb[i].w, h1, l1); \
            *(uint2*)(base + 2*TB + off) = make_uint2(h0, h1); \
            *(uint2*)(base + 3*TB + off) = make_uint2(l0, l1); \
        } } while(0)

    float c[4][4][4];
    #pragma unroll
    for (int i = 0; i < 4; i++)
        #pragma unroll
        for (int j = 0; j < 4; j++)
            #pragma unroll
            for (int q = 0; q < 4; q++) c[i][j][q] = 0.f;

    LOAD_G(0);
    STORE_S(0);
    __syncthreads();

    const int Kt = K >> 5;
    const int rowsel = lane & 15;
    const uint32_t kbhalf = (uint32_t)(lane >> 4) * 16;

    for (int it = 0; it < Kt; it++) {
        const int b = it & 1;
        const bool more = (it + 1) < Kt;
        if (more) LOAD_G((it + 1) * 32);

        const uint32_t aH = smb + (uint32_t)b*4*TB;
        const uint32_t aL = aH + TB;
        const uint32_t bH = aH + 2*TB;
        const uint32_t bL = aH + 3*TB;

        #pragma unroll
        for (int ks = 0; ks < 2; ks++) {
            const uint32_t kb = kbhalf + ks*32;
            uint32_t ah[4][4], al[4][4], bh[2][4], bl[2][4];
            #pragma unroll
            for (int mf = 0; mf < 4; mf++) {
                uint32_t ra = (uint32_t)(wm*64 + mf*16 + rowsel)*RSTRIDE + kb;
                ldm_x4(ah[mf][0], ah[mf][1], ah[mf][2], ah[mf][3], aH + ra);
                ldm_x4(al[mf][0], al[mf][1], al[mf][2], al[mf][3], aL + ra);
            }
            #pragma unroll
            for (int ng = 0; ng < 2; ng++) {
                uint32_t rb = (uint32_t)(wn*32 + ng*16 + rowsel)*RSTRIDE + kb;
                ldm_x4(bh[ng][0], bh[ng][1], bh[ng][2], bh[ng][3], bH + rb);
                ldm_x4(bl[ng][0], bl[ng][1], bl[ng][2], bl[ng][3], bL + rb);
            }
            #pragma unroll
            for (int mf = 0; mf < 4; mf++)
                #pragma unroll
                for (int nf = 0; nf < 4; nf++) {
                    const int ng = nf >> 1, s = nf & 1;
                    mma_bf16(c[mf][nf], ah[mf], bh[ng][s], bh[ng][s+2]);
                    mma_bf16(c[mf][nf], ah[mf], bl[ng][s], bl[ng][s+2]);
                    mma_bf16(c[mf][nf], al[mf], bh[ng][s], bh[ng][s+2]);
                }
        }
        if (more) { __syncthreads(); STORE_S(b ^ 1); }
        __syncthreads();
    }

    if (act == 2) {
        // stage tile (+bias) in smem, reduce 8-row groups -> C[bm/8+b][bn+c] = mean
        float* red = (float*)sm;           // [128][132]
        #pragma unroll
        for (int mf = 0; mf < 4; mf++) {
            #pragma unroll
            for (int nf = 0; nf < 4; nf++) {
                int lr = wm*64 + mf*16 + (lane >> 2);
                int cl = wn*32 + nf*8 + (lane & 3)*2;
                *(float2*)(red + lr*132 + cl) =
                    make_float2(c[mf][nf][0] + bias_s[cl], c[mf][nf][1] + bias_s[cl+1]);
                *(float2*)(red + (lr+8)*132 + cl) =
                    make_float2(c[mf][nf][2] + bias_s[cl], c[mf][nf][3] + bias_s[cl+1]);
            }
        }
        __syncthreads();
        for (int i = tid; i < 16*128; i += 256) {
            int b = i >> 7, cc = i & 127;
            float s = 0.f;
            #pragma unroll
            for (int q = 0; q < 8; q++) s += red[(b*8 + q)*132 + cc];
            C[(size_t)(bm/8 + b)*N + bn + cc] = s * 0.125f;
        }
        return;
    }

    #pragma unroll
    for (int mf = 0; mf < 4; mf++) {
        #pragma unroll
        for (int nf = 0; nf < 4; nf++) {
            int r0 = bm + wm*64 + mf*16 + (lane >> 2);
            int cl = wn*32 + nf*8 + (lane & 3)*2;
            float2 v0, v1;
            v0.x = c[mf][nf][0] + bias_s[cl];
            v0.y = c[mf][nf][1] + bias_s[cl+1];
            v1.x = c[mf][nf][2] + bias_s[cl];
            v1.y = c[mf][nf][3] + bias_s[cl+1];
            if (act == 1) {
                v0.x = tanhf(v0.x); v0.y = tanhf(v0.y);
                v1.x = tanhf(v1.x); v1.y = tanhf(v1.y);
            }
            *(float2*)(C + (size_t)r0 * N + bn + cl)       = v0;
            *(float2*)(C + (size_t)(r0 + 8) * N + bn + cl) = v1;
        }
    }
}

// ---------------- fused attention (Lk=256, D=64, packed f32x2 math) ----------
// Thread lane owns k in {2*lane + 64*jj + e}. KT/Ss rows stride 258 (8B-aligned
// LDS.64/STS.64, conflict-free). PV accumulates d-pairs (2*lane, 2*lane+1).
#define ATTN_SMEM ((64*258 + 256*64 + 64*64 + 64*258) * 4)

__global__ void __launch_bounds__(256) attn_kernel(
    const float* __restrict__ Q, const float* __restrict__ Km,
    const float* __restrict__ Vm, const float* __restrict__ dV,
    float* __restrict__ O, int lq, int kvstride)
{
    extern __shared__ __align__(16) float smf[];
    float* KT = smf;                  // [64][258] d-major
    float* V  = KT + 64*258;          // [256][64]
    float* Qs = V  + 256*64;          // [64][64]
    float* Ss = Qs + 64*64;           // [64][258] probabilities

    const int h   = blockIdx.x;
    const int r0  = blockIdx.y * 64;
    const int tid = threadIdx.x;

    for (int i = tid; i < 256*16; i += 256) {
        int k = i >> 4, dv4 = (i & 15) << 2;
        float4 kv = *(const float4*)(Km + (size_t)k*kvstride + h*64 + dv4);
        KT[(dv4+0)*258 + k] = kv.x;
        KT[(dv4+1)*258 + k] = kv.y;
        KT[(dv4+2)*258 + k] = kv.z;
        KT[(dv4+3)*258 + k] = kv.w;
        float4 vv = *(const float4*)(Vm + (size_t)k*kvstride + h*64 + dv4);
        *(float4*)(V + k*64 + dv4) = vv;
    }
    for (int i = tid; i < 64*16; i += 256) {
        int r = i >> 4, dv4 = (i & 15) << 2;
        *(float4*)(Qs + r*64 + dv4) =
            *(const float4*)(Q + (size_t)(r0 + r)*E_ + h*64 + dv4);
    }
    __syncthreads();

    const int w    = tid >> 5;
    const int lane = tid & 31;
    const int wr   = w * 8;
    const int k2   = lane * 2;        // even base k / even base d

    // scores: sp[r][jj] = f32x2 pair over (k2+64jj, k2+64jj+1)
    unsigned long long sp[8][4];
    #pragma unroll
    for (int r = 0; r < 8; r++)
        #pragma unroll
        for (int jj = 0; jj < 4; jj++) sp[r][jj] = 0ULL;

    for (int d = 0; d < 64; d++) {
        unsigned long long kk2[4];
        #pragma unroll
        for (int jj = 0; jj < 4; jj++)
            kk2[jj] = *(const unsigned long long*)(KT + d*258 + k2 + 64*jj);
        #pragma unroll
        for (int r = 0; r < 8; r++) {
            float q = Qs[(wr + r)*64 + d];
            unsigned long long qq = pk2(q, q);
            #pragma unroll
            for (int jj = 0; jj < 4; jj++) fma2(sp[r][jj], qq, kk2[jj]);
        }
    }

    // softmax over 256 k's per row
    #pragma unroll
    for (int r = 0; r < 8; r++) {
        float s[8];
        #pragma unroll
        for (int jj = 0; jj < 4; jj++) upk2(sp[r][jj], s[2*jj], s[2*jj+1]);
        float m = -1e30f;
        #pragma unroll
        for (int i = 0; i < 8; i++) { s[i] *= 0.125f; m = fmaxf(m, s[i]); }
        #pragma unroll
        for (int o = 16; o > 0; o >>= 1) m = fmaxf(m, __shfl_xor_sync(0xffffffffu, m, o));
        float sum = 0.f;
        #pragma unroll
        for (int i = 0; i < 8; i++) { s[i] = __expf(s[i] - m); sum += s[i]; }
        #pragma unroll
        for (int o = 16; o > 0; o >>= 1) sum += __shfl_xor_sync(0xffffffffu, sum, o);
        float inv = 1.f / sum;
        #pragma unroll
        for (int jj = 0; jj < 4; jj++)
            *(unsigned long long*)(Ss + (wr + r)*258 + k2 + 64*jj) =
                pk2(s[2*jj] * inv, s[2*jj+1] * inv);
    }
    __syncwarp();

    // ctx: acc[r] = f32x2 over d-pair (k2, k2+1)
    unsigned long long acc[8];
    #pragma unroll
    for (int r = 0; r < 8; r++) acc[r] = 0ULL;
    for (int k = 0; k < 256; k++) {
        unsigned long long v2 = *(const unsigned long long*)(V + k*64 + k2);
        #pragma unroll
        for (int r = 0; r < 8; r++) {
            float p = Ss[(wr + r)*258 + k];
            fma2(acc[r], pk2(p, p), v2);
        }
    }

    #pragma unroll
    for (int r = 0; r < 8; r++) {
        int row = r0 + wr + r;
        float o0, o1;
        upk2(acc[r], o0, o1);
        if (dV) {
            int b = row / lq;
            float2 dvv = *(const float2*)(dV + (size_t)b*E_ + h*64 + k2);
            o0 += dvv.x; o1 += dvv.y;
        }
        *(float2*)(O + (size_t)row*E_ + h*64 + k2) = make_float2(o0, o1);
    }
}

// ---------------- small elementwise kernel -----------------------------------
// out[b,k,e] = memory[k,e] + ma[b,e]   (the 1.07 GB output tensor)
__global__ void write_um(const float* __restrict__ mem, const float* __restrict__ ma,
                         float* __restrict__ out)
{
    size_t i = (size_t)blockIdx.x * blockDim.x + threadIdx.x;
    size_t e4 = i & 127;
    size_t k  = (i >> 7) & 255;
    size_t b  = i >> 15;
    float4 m4 = ((const float4*)mem)[k * 128 + e4];
    float4 a4 = ((const float4*)ma)[b * 128 + e4];
    ((float4*)out)[i] = make_float4(m4.x + a4.x, m4.y + a4.y, m4.z + a4.z, m4.w + a4.w);
}

// ---------------- launch ------------------------------------------------------
extern "C" void kernel_launch(void* const* d_in, const int* in_sizes, int n_in,
                              void* d_out, int out_size)
{
    const float* x     = (const float*)d_in[0];
    const float* mem   = (const float*)d_in[1];
    const float* enc_w = (const float*)d_in[2];
    const float* enc_b = (const float*)d_in[3];
    const float* blk_w = (const float*)d_in[4];
    const float* blk_b = (const float*)d_in[5];
    const float* in_w  = (const float*)d_in[6];
    const float* in_b  = (const float*)d_in[7];
    const float* out_w = (const float*)d_in[8];
    const float* out_b = (const float*)d_in[9];
    const float* dec_w = (const float*)d_in[10];
    const float* dec_b = (const float*)d_in[11];

    float* out    = (float*)d_out;                   // (B, IN)
    float* out_um = out + (size_t)B_ * IN_;          // (B, M, E)

    float *encoded, *mu, *qp1, *kpv, *ctx1, *ma, *qp2, *dv, *ctx2, *retr;
    cudaGetSymbolAddress((void**)&encoded, g_encoded);
    cudaGetSymbolAddress((void**)&mu,      g_mu);
    cudaGetSymbolAddress((void**)&qp1,     g_qp1);
    cudaGetSymbolAddress((void**)&kpv,     g_kpv);
    cudaGetSymbolAddress((void**)&ctx1,    g_ctx1);
    cudaGetSymbolAddress((void**)&ma,      g_ma);
    cudaGetSymbolAddress((void**)&qp2,     g_qp2);
    cudaGetSymbolAddress((void**)&dv,      g_dv);
    cudaGetSymbolAddress((void**)&ctx2,    g_ctx2);
    cudaGetSymbolAddress((void**)&retr,    g_retr);

    const float* wq  = in_w;
    const float* bq  = in_b;
    const float* wkv = in_w + 512*512;   // wk rows then wv rows (contiguous)
    const float* bkv = in_b + 512;       // bk then bv (contiguous)
    const float* wv  = in_w + 1024*512;

    cudaFuncSetAttribute(gemm_tc, cudaFuncAttributeMaxDynamicSharedMemorySize, GT_SMEM);
    cudaFuncSetAttribute(attn_kernel, cudaFuncAttributeMaxDynamicSharedMemorySize, ATTN_SMEM);

    dim3 thr(GT_THREADS);
    dim3 thr2(256);

    // encoded = tanh(x @ enc_w^T + enc_b)                       [2048 x 512] K=1024
    gemm_tc<<<dim3(E_/128, B_/128), thr, GT_SMEM>>>(x, enc_w, enc_b, encoded, B_, E_, IN_, 1);
    // memory_updates = encoded @ blk_w_flat^T + blk_b_flat      [2048 x 4096]
    gemm_tc<<<dim3(4096/128, B_/128), thr, GT_SMEM>>>(encoded, blk_w, blk_b, mu, B_, NB_*E_, E_, 0);
    // qp1 = mu @ wq^T + bq                                      [16384 x 512]
    gemm_tc<<<dim3(E_/128, (B_*NB_)/128), thr, GT_SMEM>>>(mu, wq, bq, qp1, B_*NB_, E_, E_, 0);
    // kp|vp = mem @ [wk;wv]^T + [bk;bv]                         [256 x 1024] one launch
    gemm_tc<<<dim3(1024/128, M_/128), thr, GT_SMEM>>>(mem, wkv, bkv, kpv, M_, 2*E_, E_, 0);
    // MHA1 attention core (K/V from kpv, row stride 1024)
    attn_kernel<<<dim3(H_, (B_*NB_)/64), thr2, ATTN_SMEM>>>(qp1, kpv, kpv + 512, nullptr, ctx1, NB_, 2*E_);
    // ma = mean_q(ctx1 @ out_w^T + out_b)  — fused reduce epilogue (act=2)
    gemm_tc<<<dim3(E_/128, (B_*NB_)/128), thr, GT_SMEM>>>(ctx1, out_w, out_b, ma, B_*NB_, E_, E_, 2);
    // updated_memory output (rank-1 expanded)
    write_um<<<((size_t)B_*M_*E_/4)/256, thr2>>>(mem, ma, out_um);
    // qp2 = encoded @ wq^T + bq                                 [2048 x 512]
    gemm_tc<<<dim3(E_/128, B_/128), thr, GT_SMEM>>>(encoded, wq, bq, qp2, B_, E_, E_, 0);
    // dv = ma @ wv^T (no bias; bias already inside vp)          [2048 x 512]
    gemm_tc<<<dim3(E_/128, B_/128), thr, GT_SMEM>>>(ma, wv, nullptr, dv, B_, E_, E_, 0);
    // MHA2 attention core (batch score term is softmax-invariant)
    attn_kernel<<<dim3(H_, B_/64), thr2, ATTN_SMEM>>>(qp2, kpv, kpv + 512, dv, ctx2, 1, 2*E_);
    // retrieved = ctx2 @ out_w^T + out_b                        [2048 x 512]
    gemm_tc<<<dim3(E_/128, B_/128), thr, GT_SMEM>>>(ctx2, out_w, out_b, retr, B_, E_, E_, 0);
    // output = retrieved @ dec_w^T + dec_b                      [2048 x 1024]
    gemm_tc<<<dim3(IN_/128, B_/128), thr, GT_SMEM>>>(retr, dec_w, dec_b, out, B_, IN_, E_, 0);
}